// round 13
// baseline (speedup 1.0000x reference)
#include <cuda_runtime.h>
#include <cuda_bf16.h>
#include <math.h>

#define D 512
#define B_GRAPHS 64
#define N_NODES 131072      // 64 * 2048
#define MAX_NODES 2048

#define GT 8                // graphs per warp tile
#define JT 8                // outputs per warp tile
#define GEMM_BLOCKS 64      // 64 blocks * 8 warps = 512 warps

// Scratch (no allocations allowed)
__device__ float g_pn[B_GRAPHS * D];

// ---------------------------------------------------------------------------
// Prologue: pn = graph_attr @ W^T + b.
// Triggers programmatic launch of the main kernel at entry; main syncs on
// grid dependency before reading g_pn.
// ---------------------------------------------------------------------------
__global__ void pn_gemm_kernel(const float* __restrict__ ga,
                               const float* __restrict__ W,
                               const float* __restrict__ bias) {
    cudaTriggerProgrammaticLaunchCompletion();   // let main kernel start now

    const int w    = blockIdx.x * 8 + (threadIdx.x >> 5);  // 0..511
    const int lane = threadIdx.x & 31;
    const int g0   = (w >> 6) * GT;        // 0,8,...,56
    const int j0   = (w & 63) * JT;        // 0,8,...,504

    const float4* __restrict__ ga4 = reinterpret_cast<const float4*>(ga);
    const float4* __restrict__ W4  = reinterpret_cast<const float4*>(W);

    float v[GT * JT];
#pragma unroll
    for (int i = 0; i < GT * JT; i++) v[i] = 0.0f;

#pragma unroll
    for (int t = 0; t < 4; t++) {
        const int f = lane + 32 * t;
        float4 a[GT];
#pragma unroll
        for (int gg = 0; gg < GT; gg++)
            a[gg] = ga4[(g0 + gg) * 128 + f];
#pragma unroll
        for (int jj = 0; jj < JT; jj++) {
            float4 wv = W4[(j0 + jj) * 128 + f];
#pragma unroll
            for (int gg = 0; gg < GT; gg++) {
                v[gg * JT + jj] += a[gg].x * wv.x + a[gg].y * wv.y
                                 + a[gg].z * wv.z + a[gg].w * wv.w;
            }
        }
    }

    // Distributed butterfly reduce: 64 values -> 2 fully-reduced per lane.
    int cnt = GT * JT;
#pragma unroll
    for (int o = 1; o <= 16; o <<= 1) {
        cnt >>= 1;
        const bool hi = (lane & o) != 0;
#pragma unroll
        for (int i = 0; i < 32; i++) {
            if (i >= cnt) break;
            float send = hi ? v[i] : v[i + cnt];
            float recv = __shfl_xor_sync(0xFFFFFFFFu, send, o);
            v[i] = (hi ? v[i + cnt] : v[i]) + recv;
        }
    }

    // lane owns orig indices 2*bitrev5(lane) + {0,1}
    const int R = ((lane & 1) << 4) | ((lane & 2) << 2) | (lane & 4)
                | ((lane & 8) >> 2) | ((lane & 16) >> 4);
#pragma unroll
    for (int i = 0; i < 2; i++) {
        const int orig = 2 * R + i;
        const int gg = orig >> 3;
        const int jj = orig & 7;
        g_pn[(g0 + gg) * D + j0 + jj] = v[i] + bias[j0 + jj];
    }
}

// ---------------------------------------------------------------------------
// Main kernel: half-warp (16 lanes) per node. 4+4 load batches, 4 accumulator
// chains, 4-level shuffle reduce. pos = n - g*MAX_NODES (sorted equal-size).
// PDL: x loads issued before the grid-dependency sync; pn only after.
// ---------------------------------------------------------------------------
__global__ void __launch_bounds__(256, 7)
node_sim_kernel(const float* __restrict__ x,
                const int* __restrict__ batch,
                const float* __restrict__ temp,
                float* __restrict__ out) {
    const int warp = (blockIdx.x * blockDim.x + threadIdx.x) >> 5;
    const int lane = threadIdx.x & 31;
    const int half = lane >> 4;          // 0 or 1
    const int s    = lane & 15;
    const int n    = warp * 2 + half;
    if (n >= N_NODES) { cudaGridDependencySynchronize(); return; }

    const int g = batch[n];              // input: independent of GEMM

    const float4* __restrict__ xr =
        reinterpret_cast<const float4*>(x) + (size_t)n * 128;

    // Issue first x batch before waiting on the GEMM grid.
    float4 x0 = __ldcs(&xr[s +  0]);
    float4 x1 = __ldcs(&xr[s + 16]);
    float4 x2 = __ldcs(&xr[s + 32]);
    float4 x3 = __ldcs(&xr[s + 48]);

    cudaGridDependencySynchronize();     // g_pn now complete & visible

    const float4* __restrict__ pr =
        reinterpret_cast<const float4*>(g_pn) + (size_t)g * 128;

    float a0 = 0.0f, a1 = 0.0f, a2 = 0.0f, a3 = 0.0f;
    float d;
    {
        float4 p0 = pr[s +  0];
        float4 p1 = pr[s + 16];
        float4 p2 = pr[s + 32];
        float4 p3 = pr[s + 48];
        d = x0.x - p0.x; a0 += d * d;  d = x0.y - p0.y; a0 += d * d;
        d = x0.z - p0.z; a0 += d * d;  d = x0.w - p0.w; a0 += d * d;
        d = x1.x - p1.x; a1 += d * d;  d = x1.y - p1.y; a1 += d * d;
        d = x1.z - p1.z; a1 += d * d;  d = x1.w - p1.w; a1 += d * d;
        d = x2.x - p2.x; a2 += d * d;  d = x2.y - p2.y; a2 += d * d;
        d = x2.z - p2.z; a2 += d * d;  d = x2.w - p2.w; a2 += d * d;
        d = x3.x - p3.x; a3 += d * d;  d = x3.y - p3.y; a3 += d * d;
        d = x3.z - p3.z; a3 += d * d;  d = x3.w - p3.w; a3 += d * d;
    }
    {
        float4 y0 = __ldcs(&xr[s +  64]);
        float4 y1 = __ldcs(&xr[s +  80]);
        float4 y2 = __ldcs(&xr[s +  96]);
        float4 y3 = __ldcs(&xr[s + 112]);
        float4 p0 = pr[s +  64];
        float4 p1 = pr[s +  80];
        float4 p2 = pr[s +  96];
        float4 p3 = pr[s + 112];
        d = y0.x - p0.x; a0 += d * d;  d = y0.y - p0.y; a0 += d * d;
        d = y0.z - p0.z; a0 += d * d;  d = y0.w - p0.w; a0 += d * d;
        d = y1.x - p1.x; a1 += d * d;  d = y1.y - p1.y; a1 += d * d;
        d = y1.z - p1.z; a1 += d * d;  d = y1.w - p1.w; a1 += d * d;
        d = y2.x - p2.x; a2 += d * d;  d = y2.y - p2.y; a2 += d * d;
        d = y2.z - p2.z; a2 += d * d;  d = y2.w - p2.w; a2 += d * d;
        d = y3.x - p3.x; a3 += d * d;  d = y3.y - p3.y; a3 += d * d;
        d = y3.z - p3.z; a3 += d * d;  d = y3.w - p3.w; a3 += d * d;
    }

    float acc = (a0 + a1) + (a2 + a3);
#pragma unroll
    for (int o = 8; o > 0; o >>= 1)
        acc += __shfl_xor_sync(0xFFFFFFFFu, acc, o);

    if (s == 0) {
        const int pos = n - g * MAX_NODES;   // sorted equal-size segments
        out[(size_t)g * MAX_NODES + pos] = -sqrtf(acc) / temp[0];
    }
}

// ---------------------------------------------------------------------------
extern "C" void kernel_launch(void* const* d_in, const int* in_sizes, int n_in,
                              void* d_out, int out_size) {
    const float* x     = (const float*)d_in[0];   // [N, D]
    const float* ga    = (const float*)d_in[1];   // [B, D]
    const int*   batch = (const int*)d_in[2];     // [N]
    const float* W     = (const float*)d_in[3];   // [D, D]
    const float* bias  = (const float*)d_in[4];   // [D]
    const float* temp  = (const float*)d_in[5];   // [1]
    float* out = (float*)d_out;                   // [B, MAX_NODES, 1]

    pn_gemm_kernel<<<GEMM_BLOCKS, 256>>>(ga, W, bias);

    cudaLaunchConfig_t cfg = {};
    cfg.gridDim  = dim3(N_NODES / 16);
    cfg.blockDim = dim3(256);
    cudaLaunchAttribute attr[1];
    attr[0].id = cudaLaunchAttributeProgrammaticStreamSerialization;
    attr[0].val.programmaticStreamSerializationAllowed = 1;
    cfg.attrs = attr;
    cfg.numAttrs = 1;
    cudaLaunchKernelEx(&cfg, node_sim_kernel, x, batch, temp, out);
}